// round 2
// baseline (speedup 1.0000x reference)
#include <cuda_runtime.h>
#include <cuda_bf16.h>

// ---------------------------------------------------------------------------
// QCNNHybrid R2:
//  k_stats : 512 blocks x 256 thr, 8 rows/thread, deterministic partials.
//  k_fold  : reduce partials, fold BN into layer-1, write ALL params as
//            duplicated f32x2 (u64) in layout [bias][w0..wDIN-1] per output.
//  k_main  : 1 pack (2 rows)/thread, LDS.64 weight feeds fma.rn.f32x2
//            directly, low register pressure -> high occupancy.
// ---------------------------------------------------------------------------

#define NBLK_STATS 512
#define NTHREADS   256

__device__ float g_partials[NBLK_STATS * 16];

// u64 (duplicated-pair) layout, per layer: DOUT groups of (1 bias + DIN weights)
#define U_FM 0      // 8->16  : 144
#define U_C1 144    // 16->16 : 272
#define U_P1 416    // 16->12 : 204
#define U_C2 620    // 12->8  : 104
#define U_P2 724    // 8->4   : 36
#define U_C3 760    // 4->4   : 20
#define U_R  780    // 4->4   : 20
#define U_H  800    // 4->1   : 5
#define U_TOTAL 805
__device__ float2 g_w[U_TOTAL];

typedef unsigned long long u64;

// ------------------------------- f32x2 helpers -----------------------------
__device__ __forceinline__ u64 pk2(float a, float b) {
    u64 r;
    asm("mov.b64 %0,{%1,%2};" : "=l"(r) : "f"(a), "f"(b));
    return r;
}
__device__ __forceinline__ void upk2(u64 v, float& a, float& b) {
    asm("mov.b64 {%0,%1},%2;" : "=f"(a), "=f"(b) : "l"(v));
}
__device__ __forceinline__ u64 ffma2(u64 a, u64 b, u64 c) {
    u64 d;
    asm("fma.rn.f32x2 %0,%1,%2,%3;" : "=l"(d) : "l"(a), "l"(b), "l"(c));
    return d;
}
__device__ __forceinline__ u64 fadd2(u64 a, u64 b) {
    u64 d;
    asm("add.rn.f32x2 %0,%1,%2;" : "=l"(d) : "l"(a), "l"(b));
    return d;
}
__device__ __forceinline__ float tanh_ap(float x) {
    float y;
    asm("tanh.approx.f32 %0,%1;" : "=f"(y) : "f"(x));
    return y;
}
__device__ __forceinline__ u64 tanh2(u64 v) {
    float a, b;
    upk2(v, a, b);
    return pk2(tanh_ap(a), tanh_ap(b));
}
__device__ __forceinline__ u64 relu2(u64 v) {
    float a, b;
    upk2(v, a, b);
    return pk2(fmaxf(a, 0.0f), fmaxf(b, 0.0f));
}

// one dense layer on one f32x2 pack (2 rows); weights pre-duplicated in SMEM
template <int DIN, int DOUT, int BASE, bool ACT>
__device__ __forceinline__ void layerP(const u64* __restrict__ sw,
                                       const u64* __restrict__ a,
                                       u64* __restrict__ o) {
#pragma unroll
    for (int j = 0; j < DOUT; j++) {
        u64 acc = sw[BASE + j * (DIN + 1)];           // duplicated bias
#pragma unroll
        for (int i = 0; i < DIN; i++)
            acc = ffma2(a[i], sw[BASE + j * (DIN + 1) + 1 + i], acc);
        if (ACT) acc = tanh2(acc);
        o[j] = acc;
    }
}

// ------------------------------- kernel A: stats ---------------------------
__global__ void __launch_bounds__(NTHREADS) k_stats(const float* __restrict__ x,
                                                    int nrows) {
    int g = blockIdx.x * NTHREADS + threadIdx.x;
    long base = (long)g * 8;                          // 8 rows per thread
    float s[8], q[8];
#pragma unroll
    for (int c = 0; c < 8; c++) { s[c] = 0.0f; q[c] = 0.0f; }
    if (base + 7 < nrows) {
        const float4* xv = (const float4*)(x + base * 8);
#pragma unroll
        for (int r = 0; r < 8; r++) {
            float4 a = xv[r * 2], b = xv[r * 2 + 1];
            s[0] += a.x; q[0] = fmaf(a.x, a.x, q[0]);
            s[1] += a.y; q[1] = fmaf(a.y, a.y, q[1]);
            s[2] += a.z; q[2] = fmaf(a.z, a.z, q[2]);
            s[3] += a.w; q[3] = fmaf(a.w, a.w, q[3]);
            s[4] += b.x; q[4] = fmaf(b.x, b.x, q[4]);
            s[5] += b.y; q[5] = fmaf(b.y, b.y, q[5]);
            s[6] += b.z; q[6] = fmaf(b.z, b.z, q[6]);
            s[7] += b.w; q[7] = fmaf(b.w, b.w, q[7]);
        }
    }
#pragma unroll
    for (int c = 0; c < 8; c++) {
#pragma unroll
        for (int o = 16; o > 0; o >>= 1) {
            s[c] += __shfl_xor_sync(0xffffffffu, s[c], o);
            q[c] += __shfl_xor_sync(0xffffffffu, q[c], o);
        }
    }
    __shared__ float sm[8][16];
    int warp = threadIdx.x >> 5, lane = threadIdx.x & 31;
    if (lane == 0) {
#pragma unroll
        for (int c = 0; c < 8; c++) { sm[warp][c] = s[c]; sm[warp][8 + c] = q[c]; }
    }
    __syncthreads();
    if (threadIdx.x < 16) {
        float acc = 0.0f;
#pragma unroll
        for (int w = 0; w < 8; w++) acc += sm[w][threadIdx.x];
        g_partials[blockIdx.x * 16 + threadIdx.x] = acc;
    }
}

// ------------------------------- kernel B: fold ----------------------------
__device__ __forceinline__ void dup_layer(int tid, int base, int din, int dout,
                                          const float* __restrict__ W,
                                          const float* __restrict__ Bv) {
    int n = dout * (din + 1);
    for (int idx = tid; idx < n; idx += NTHREADS) {
        int j = idx / (din + 1);
        int k = idx - j * (din + 1);
        float v = (k == 0) ? Bv[j] : W[(k - 1) * dout + j];
        g_w[base + idx] = make_float2(v, v);
    }
}

__global__ void __launch_bounds__(NTHREADS) k_fold(
    const float* __restrict__ bn_g, const float* __restrict__ bn_b,
    const float* __restrict__ w_fm, const float* __restrict__ b_fm,
    const float* __restrict__ w_c1, const float* __restrict__ b_c1,
    const float* __restrict__ w_p1, const float* __restrict__ b_p1,
    const float* __restrict__ w_c2, const float* __restrict__ b_c2,
    const float* __restrict__ w_p2, const float* __restrict__ b_p2,
    const float* __restrict__ w_c3, const float* __restrict__ b_c3,
    const float* __restrict__ w_r,  const float* __restrict__ b_r,
    const float* __restrict__ w_h,  const float* __restrict__ b_h,
    float invB) {
    int tid = threadIdx.x;
    __shared__ float s1[256];
    __shared__ float totals[16];
    __shared__ float scale[8], shift[8];

    // reduce 512 block-partials: 16 chunks x 16 columns
    {
        int col = tid >> 4, chunk = tid & 15;
        int per = NBLK_STATS / 16;                    // 32
        int b0 = chunk * per;
        float acc = 0.0f;
        for (int b = b0; b < b0 + per; b++) acc += g_partials[b * 16 + col];
        s1[col * 16 + chunk] = acc;
    }
    __syncthreads();
    if (tid < 16) {
        float acc = 0.0f;
#pragma unroll
        for (int k = 0; k < 16; k++) acc += s1[tid * 16 + k];
        totals[tid] = acc;
    }
    __syncthreads();
    if (tid < 8) {
        float mu = totals[tid] * invB;
        float var = totals[8 + tid] * invB - mu * mu;
        float sc = bn_g[tid] * rsqrtf(var + 1e-5f);
        scale[tid] = sc;
        shift[tid] = bn_b[tid] - mu * sc;
    }
    __syncthreads();

    // folded first layer (BN absorbed), duplicated layout
    for (int idx = tid; idx < 16 * 9; idx += NTHREADS) {
        int j = idx / 9, k = idx - j * 9;
        float v;
        if (k == 0) {
            v = b_fm[j];
#pragma unroll
            for (int i = 0; i < 8; i++) v += shift[i] * w_fm[i * 16 + j];
        } else {
            v = scale[k - 1] * w_fm[(k - 1) * 16 + j];
        }
        g_w[U_FM + idx] = make_float2(v, v);
    }
    dup_layer(tid, U_C1, 16, 16, w_c1, b_c1);
    dup_layer(tid, U_P1, 16, 12, w_p1, b_p1);
    dup_layer(tid, U_C2, 12, 8,  w_c2, b_c2);
    dup_layer(tid, U_P2, 8,  4,  w_p2, b_p2);
    dup_layer(tid, U_C3, 4,  4,  w_c3, b_c3);
    dup_layer(tid, U_R,  4,  4,  w_r,  b_r);
    dup_layer(tid, U_H,  4,  1,  w_h,  b_h);
}

// ------------------------------- kernel C: main ----------------------------
__global__ void __launch_bounds__(NTHREADS, 2) k_main(const float* __restrict__ x,
                                                      float* __restrict__ out,
                                                      int nrows) {
    __shared__ u64 sw[U_TOTAL];
    {
        const u64* gw = (const u64*)g_w;
        for (int i = threadIdx.x; i < U_TOTAL; i += NTHREADS) sw[i] = gw[i];
    }
    __syncthreads();

    int t = blockIdx.x * NTHREADS + threadIdx.x;
    long base = (long)t * 2;                          // 2 rows per thread
    if (base >= nrows) return;

    const float4* xv = (const float4*)(x + base * 8);
    float4 r0a = xv[0], r0b = xv[1];
    float4 r1a = xv[2], r1b = xv[3];

    u64 A[16], B[16];
    A[0] = pk2(r0a.x, r1a.x);
    A[1] = pk2(r0a.y, r1a.y);
    A[2] = pk2(r0a.z, r1a.z);
    A[3] = pk2(r0a.w, r1a.w);
    A[4] = pk2(r0b.x, r1b.x);
    A[5] = pk2(r0b.y, r1b.y);
    A[6] = pk2(r0b.z, r1b.z);
    A[7] = pk2(r0b.w, r1b.w);

    layerP<8, 16, U_FM, true>(sw, A, B);   // feature_map (BN folded)
    layerP<16, 16, U_C1, true>(sw, B, A);  // conv1
    layerP<16, 12, U_P1, true>(sw, A, B);  // pool1
    layerP<12, 8, U_C2, true>(sw, B, A);   // conv2
    layerP<8, 4, U_P2, true>(sw, A, B);    // pool2
    layerP<4, 4, U_C3, true>(sw, B, A);    // conv3 -> A[0..3]
    layerP<4, 4, U_R, false>(sw, A, B);    // residual pre-relu
#pragma unroll
    for (int j = 0; j < 4; j++) A[j] = fadd2(A[j], relu2(B[j]));

    // head [4->1], sigmoid(x) = 0.5*tanh(0.5x)+0.5
    u64 acc = sw[U_H];
#pragma unroll
    for (int i = 0; i < 4; i++) acc = ffma2(A[i], sw[U_H + 1 + i], acc);
    float z0, z1;
    upk2(acc, z0, z1);
    float2 o;
    o.x = fmaf(0.5f, tanh_ap(0.5f * z0), 0.5f);
    o.y = fmaf(0.5f, tanh_ap(0.5f * z1), 0.5f);
    ((float2*)out)[t] = o;
}

// ------------------------------- launch ------------------------------------
extern "C" void kernel_launch(void* const* d_in, const int* in_sizes, int n_in,
                              void* d_out, int out_size) {
    const float* x    = (const float*)d_in[0];
    const float* bn_g = (const float*)d_in[1];
    const float* bn_b = (const float*)d_in[2];
    const float* w_fm = (const float*)d_in[3];
    const float* b_fm = (const float*)d_in[4];
    const float* w_c1 = (const float*)d_in[5];
    const float* b_c1 = (const float*)d_in[6];
    const float* w_p1 = (const float*)d_in[7];
    const float* b_p1 = (const float*)d_in[8];
    const float* w_c2 = (const float*)d_in[9];
    const float* b_c2 = (const float*)d_in[10];
    const float* w_p2 = (const float*)d_in[11];
    const float* b_p2 = (const float*)d_in[12];
    const float* w_c3 = (const float*)d_in[13];
    const float* b_c3 = (const float*)d_in[14];
    const float* w_r  = (const float*)d_in[15];
    const float* b_r  = (const float*)d_in[16];
    const float* w_h  = (const float*)d_in[17];
    const float* b_h  = (const float*)d_in[18];
    float* out = (float*)d_out;

    int nrows = in_sizes[0] / 8;                      // 1048576

    k_stats<<<NBLK_STATS, NTHREADS>>>(x, nrows);      // 512*256*8 rows
    k_fold<<<1, NTHREADS>>>(bn_g, bn_b, w_fm, b_fm, w_c1, b_c1, w_p1, b_p1,
                            w_c2, b_c2, w_p2, b_p2, w_c3, b_c3, w_r, b_r,
                            w_h, b_h, 1.0f / (float)nrows);
    int nthreads_main = nrows / 2;                    // 524288
    k_main<<<nthreads_main / NTHREADS, NTHREADS>>>(x, out, nrows);
}

// round 3
// speedup vs baseline: 1.0612x; 1.0612x over previous
#include <cuda_runtime.h>
#include <cuda_bf16.h>

// ---------------------------------------------------------------------------
// QCNNHybrid R3:
//  k_stats : 1024 blocks x 256 thr, 4 rows/thread, loads front-batched into
//            distinct registers (MLP=8) before accumulation.
//  k_fold  : reduce partials, fold BN into layer-1, write ALL params as
//            duplicated f32x2 (u64), layout [bias][w...] per output.
//  k_main  : 128 thr/block, 2 packs (4 rows)/thread -> each weight LDS.64
//            feeds 2 fma.rn.f32x2 (4 rows). FMA-pipe bound by design.
// ---------------------------------------------------------------------------

#define NBLK_STATS 1024
#define NT_STATS   256
#define NT_MAIN    128

__device__ float g_partials[NBLK_STATS * 16];

// u64 (duplicated-pair) layout, per layer: DOUT groups of (1 bias + DIN weights)
#define U_FM 0      // 8->16  : 144
#define U_C1 144    // 16->16 : 272
#define U_P1 416    // 16->12 : 204
#define U_C2 620    // 12->8  : 104
#define U_P2 724    // 8->4   : 36
#define U_C3 760    // 4->4   : 20
#define U_R  780    // 4->4   : 20
#define U_H  800    // 4->1   : 5
#define U_TOTAL 805
__device__ float2 g_w[U_TOTAL];

typedef unsigned long long u64;

// ------------------------------- f32x2 helpers -----------------------------
__device__ __forceinline__ u64 pk2(float a, float b) {
    u64 r;
    asm("mov.b64 %0,{%1,%2};" : "=l"(r) : "f"(a), "f"(b));
    return r;
}
__device__ __forceinline__ void upk2(u64 v, float& a, float& b) {
    asm("mov.b64 {%0,%1},%2;" : "=f"(a), "=f"(b) : "l"(v));
}
__device__ __forceinline__ u64 ffma2(u64 a, u64 b, u64 c) {
    u64 d;
    asm("fma.rn.f32x2 %0,%1,%2,%3;" : "=l"(d) : "l"(a), "l"(b), "l"(c));
    return d;
}
__device__ __forceinline__ u64 fadd2(u64 a, u64 b) {
    u64 d;
    asm("add.rn.f32x2 %0,%1,%2;" : "=l"(d) : "l"(a), "l"(b));
    return d;
}
__device__ __forceinline__ float tanh_ap(float x) {
    float y;
    asm("tanh.approx.f32 %0,%1;" : "=f"(y) : "f"(x));
    return y;
}
__device__ __forceinline__ u64 tanh2(u64 v) {
    float a, b;
    upk2(v, a, b);
    return pk2(tanh_ap(a), tanh_ap(b));
}
__device__ __forceinline__ u64 relu2(u64 v) {
    float a, b;
    upk2(v, a, b);
    return pk2(fmaxf(a, 0.0f), fmaxf(b, 0.0f));
}

// one dense layer on two f32x2 packs (4 rows); each weight LDS.64 is shared
// by both packs (2 FFMA2 per LDS).
template <int DIN, int DOUT, int BASE, bool ACT>
__device__ __forceinline__ void layer2P(const u64* __restrict__ sw,
                                        const u64* __restrict__ a0,
                                        const u64* __restrict__ a1,
                                        u64* __restrict__ o0,
                                        u64* __restrict__ o1) {
#pragma unroll
    for (int j = 0; j < DOUT; j++) {
        u64 acc0 = sw[BASE + j * (DIN + 1)];          // duplicated bias
        u64 acc1 = acc0;
#pragma unroll
        for (int i = 0; i < DIN; i++) {
            u64 w = sw[BASE + j * (DIN + 1) + 1 + i];
            acc0 = ffma2(a0[i], w, acc0);
            acc1 = ffma2(a1[i], w, acc1);
        }
        if (ACT) { acc0 = tanh2(acc0); acc1 = tanh2(acc1); }
        o0[j] = acc0;
        o1[j] = acc1;
    }
}

// ------------------------------- kernel A: stats ---------------------------
__global__ void __launch_bounds__(NT_STATS) k_stats(const float* __restrict__ x,
                                                    int nrows) {
    int g = blockIdx.x * NT_STATS + threadIdx.x;
    long base = (long)g * 4;                          // 4 rows per thread
    float s[8], q[8];
#pragma unroll
    for (int c = 0; c < 8; c++) { s[c] = 0.0f; q[c] = 0.0f; }
    if (base + 3 < nrows) {
        const float4* xv = (const float4*)(x + base * 8);
        // phase 1: issue ALL loads into distinct registers (MLP = 8)
        float4 v[8];
#pragma unroll
        for (int k = 0; k < 8; k++) v[k] = xv[k];
        // phase 2: accumulate
#pragma unroll
        for (int r = 0; r < 4; r++) {
            float4 a = v[r * 2], b = v[r * 2 + 1];
            s[0] += a.x; q[0] = fmaf(a.x, a.x, q[0]);
            s[1] += a.y; q[1] = fmaf(a.y, a.y, q[1]);
            s[2] += a.z; q[2] = fmaf(a.z, a.z, q[2]);
            s[3] += a.w; q[3] = fmaf(a.w, a.w, q[3]);
            s[4] += b.x; q[4] = fmaf(b.x, b.x, q[4]);
            s[5] += b.y; q[5] = fmaf(b.y, b.y, q[5]);
            s[6] += b.z; q[6] = fmaf(b.z, b.z, q[6]);
            s[7] += b.w; q[7] = fmaf(b.w, b.w, q[7]);
        }
    }
#pragma unroll
    for (int c = 0; c < 8; c++) {
#pragma unroll
        for (int o = 16; o > 0; o >>= 1) {
            s[c] += __shfl_xor_sync(0xffffffffu, s[c], o);
            q[c] += __shfl_xor_sync(0xffffffffu, q[c], o);
        }
    }
    __shared__ float sm[8][16];
    int warp = threadIdx.x >> 5, lane = threadIdx.x & 31;
    if (lane == 0) {
#pragma unroll
        for (int c = 0; c < 8; c++) { sm[warp][c] = s[c]; sm[warp][8 + c] = q[c]; }
    }
    __syncthreads();
    if (threadIdx.x < 16) {
        float acc = 0.0f;
#pragma unroll
        for (int w = 0; w < 8; w++) acc += sm[w][threadIdx.x];
        g_partials[blockIdx.x * 16 + threadIdx.x] = acc;
    }
}

// ------------------------------- kernel B: fold ----------------------------
__device__ __forceinline__ void dup_layer(int tid, int base, int din, int dout,
                                          const float* __restrict__ W,
                                          const float* __restrict__ Bv) {
    int n = dout * (din + 1);
    for (int idx = tid; idx < n; idx += 256) {
        int j = idx / (din + 1);
        int k = idx - j * (din + 1);
        float v = (k == 0) ? Bv[j] : W[(k - 1) * dout + j];
        g_w[base + idx] = make_float2(v, v);
    }
}

__global__ void __launch_bounds__(256) k_fold(
    const float* __restrict__ bn_g, const float* __restrict__ bn_b,
    const float* __restrict__ w_fm, const float* __restrict__ b_fm,
    const float* __restrict__ w_c1, const float* __restrict__ b_c1,
    const float* __restrict__ w_p1, const float* __restrict__ b_p1,
    const float* __restrict__ w_c2, const float* __restrict__ b_c2,
    const float* __restrict__ w_p2, const float* __restrict__ b_p2,
    const float* __restrict__ w_c3, const float* __restrict__ b_c3,
    const float* __restrict__ w_r,  const float* __restrict__ b_r,
    const float* __restrict__ w_h,  const float* __restrict__ b_h,
    float invB) {
    int tid = threadIdx.x;
    __shared__ float s1[256];
    __shared__ float totals[16];
    __shared__ float scale[8], shift[8];

    // reduce 1024 block-partials: 16 chunks x 16 columns
    {
        int col = tid >> 4, chunk = tid & 15;
        int per = NBLK_STATS / 16;                    // 64
        int b0 = chunk * per;
        float acc = 0.0f;
        for (int b = b0; b < b0 + per; b++) acc += g_partials[b * 16 + col];
        s1[col * 16 + chunk] = acc;
    }
    __syncthreads();
    if (tid < 16) {
        float acc = 0.0f;
#pragma unroll
        for (int k = 0; k < 16; k++) acc += s1[tid * 16 + k];
        totals[tid] = acc;
    }
    __syncthreads();
    if (tid < 8) {
        float mu = totals[tid] * invB;
        float var = totals[8 + tid] * invB - mu * mu;
        float sc = bn_g[tid] * rsqrtf(var + 1e-5f);
        scale[tid] = sc;
        shift[tid] = bn_b[tid] - mu * sc;
    }
    __syncthreads();

    // folded first layer (BN absorbed), duplicated layout
    for (int idx = tid; idx < 16 * 9; idx += 256) {
        int j = idx / 9, k = idx - j * 9;
        float v;
        if (k == 0) {
            v = b_fm[j];
#pragma unroll
            for (int i = 0; i < 8; i++) v += shift[i] * w_fm[i * 16 + j];
        } else {
            v = scale[k - 1] * w_fm[(k - 1) * 16 + j];
        }
        g_w[U_FM + idx] = make_float2(v, v);
    }
    dup_layer(tid, U_C1, 16, 16, w_c1, b_c1);
    dup_layer(tid, U_P1, 16, 12, w_p1, b_p1);
    dup_layer(tid, U_C2, 12, 8,  w_c2, b_c2);
    dup_layer(tid, U_P2, 8,  4,  w_p2, b_p2);
    dup_layer(tid, U_C3, 4,  4,  w_c3, b_c3);
    dup_layer(tid, U_R,  4,  4,  w_r,  b_r);
    dup_layer(tid, U_H,  4,  1,  w_h,  b_h);
}

// ------------------------------- kernel C: main ----------------------------
__global__ void __launch_bounds__(NT_MAIN) k_main(const float* __restrict__ x,
                                                  float* __restrict__ out,
                                                  int nrows) {
    __shared__ u64 sw[U_TOTAL];
    {
        const u64* gw = (const u64*)g_w;
        for (int i = threadIdx.x; i < U_TOTAL; i += NT_MAIN) sw[i] = gw[i];
    }
    __syncthreads();

    int t = blockIdx.x * NT_MAIN + threadIdx.x;
    long base = (long)t * 4;                          // 4 rows per thread
    if (base >= nrows) return;

    const float4* xv = (const float4*)(x + base * 8);
    float4 r0a = xv[0], r0b = xv[1];
    float4 r1a = xv[2], r1b = xv[3];
    float4 r2a = xv[4], r2b = xv[5];
    float4 r3a = xv[6], r3b = xv[7];

    u64 A0[16], A1[16], B0[16], B1[16];
    A0[0] = pk2(r0a.x, r1a.x); A1[0] = pk2(r2a.x, r3a.x);
    A0[1] = pk2(r0a.y, r1a.y); A1[1] = pk2(r2a.y, r3a.y);
    A0[2] = pk2(r0a.z, r1a.z); A1[2] = pk2(r2a.z, r3a.z);
    A0[3] = pk2(r0a.w, r1a.w); A1[3] = pk2(r2a.w, r3a.w);
    A0[4] = pk2(r0b.x, r1b.x); A1[4] = pk2(r2b.x, r3b.x);
    A0[5] = pk2(r0b.y, r1b.y); A1[5] = pk2(r2b.y, r3b.y);
    A0[6] = pk2(r0b.z, r1b.z); A1[6] = pk2(r2b.z, r3b.z);
    A0[7] = pk2(r0b.w, r1b.w); A1[7] = pk2(r2b.w, r3b.w);

    layer2P<8, 16, U_FM, true>(sw, A0, A1, B0, B1);   // feature_map (BN folded)
    layer2P<16, 16, U_C1, true>(sw, B0, B1, A0, A1);  // conv1
    layer2P<16, 12, U_P1, true>(sw, A0, A1, B0, B1);  // pool1
    layer2P<12, 8, U_C2, true>(sw, B0, B1, A0, A1);   // conv2
    layer2P<8, 4, U_P2, true>(sw, A0, A1, B0, B1);    // pool2
    layer2P<4, 4, U_C3, true>(sw, B0, B1, A0, A1);    // conv3 -> A[0..3]
    layer2P<4, 4, U_R, false>(sw, A0, A1, B0, B1);    // residual pre-relu
#pragma unroll
    for (int j = 0; j < 4; j++) {
        A0[j] = fadd2(A0[j], relu2(B0[j]));
        A1[j] = fadd2(A1[j], relu2(B1[j]));
    }

    // head [4->1], sigmoid(x) = 0.5*tanh(0.5x)+0.5
    u64 acc0 = sw[U_H], acc1 = acc0;
#pragma unroll
    for (int i = 0; i < 4; i++) {
        u64 w = sw[U_H + 1 + i];
        acc0 = ffma2(A0[i], w, acc0);
        acc1 = ffma2(A1[i], w, acc1);
    }
    float z0, z1, z2, z3;
    upk2(acc0, z0, z1);
    upk2(acc1, z2, z3);
    float4 o;
    o.x = fmaf(0.5f, tanh_ap(0.5f * z0), 0.5f);
    o.y = fmaf(0.5f, tanh_ap(0.5f * z1), 0.5f);
    o.z = fmaf(0.5f, tanh_ap(0.5f * z2), 0.5f);
    o.w = fmaf(0.5f, tanh_ap(0.5f * z3), 0.5f);
    ((float4*)out)[t] = o;
}

// ------------------------------- launch ------------------------------------
extern "C" void kernel_launch(void* const* d_in, const int* in_sizes, int n_in,
                              void* d_out, int out_size) {
    const float* x    = (const float*)d_in[0];
    const float* bn_g = (const float*)d_in[1];
    const float* bn_b = (const float*)d_in[2];
    const float* w_fm = (const float*)d_in[3];
    const float* b_fm = (const float*)d_in[4];
    const float* w_c1 = (const float*)d_in[5];
    const float* b_c1 = (const float*)d_in[6];
    const float* w_p1 = (const float*)d_in[7];
    const float* b_p1 = (const float*)d_in[8];
    const float* w_c2 = (const float*)d_in[9];
    const float* b_c2 = (const float*)d_in[10];
    const float* w_p2 = (const float*)d_in[11];
    const float* b_p2 = (const float*)d_in[12];
    const float* w_c3 = (const float*)d_in[13];
    const float* b_c3 = (const float*)d_in[14];
    const float* w_r  = (const float*)d_in[15];
    const float* b_r  = (const float*)d_in[16];
    const float* w_h  = (const float*)d_in[17];
    const float* b_h  = (const float*)d_in[18];
    float* out = (float*)d_out;

    int nrows = in_sizes[0] / 8;                      // 1048576

    k_stats<<<NBLK_STATS, NT_STATS>>>(x, nrows);      // 1024*256*4 rows
    k_fold<<<1, 256>>>(bn_g, bn_b, w_fm, b_fm, w_c1, b_c1, w_p1, b_p1,
                       w_c2, b_c2, w_p2, b_p2, w_c3, b_c3, w_r, b_r,
                       w_h, b_h, 1.0f / (float)nrows);
    int nthreads_main = nrows / 4;                    // 262144
    k_main<<<nthreads_main / NT_MAIN, NT_MAIN>>>(x, out, nrows);
}

// round 4
// speedup vs baseline: 1.0841x; 1.0216x over previous
#include <cuda_runtime.h>
#include <cuda_bf16.h>

// ---------------------------------------------------------------------------
// QCNNHybrid R4:
//  k_statsfold : stats with asm-pinned MLP=8 LDGs; last block (atomic ticket)
//                reduces partials with 8 indep accumulators, folds BN into
//                layer-1, writes duplicated f32x2 params (layout B).
//  k_main      : 2 packs (4 rows)/thread; biases separate from weights so
//                weight pairs load as aligned LDS.128 (ulonglong2).
// ---------------------------------------------------------------------------

#define NBLK_STATS 1024
#define NT_STATS   256
#define NT_MAIN    128

__device__ float g_partials[NBLK_STATS * 16];
__device__ unsigned int g_ticket;

// layout B (u64 units): per layer [bias x DOUT][weights j-major: DOUT x DIN]
#define FM_B 0
#define FM_W 16     // 16 + 128 = 144
#define C1_B 144
#define C1_W 160    // + 256 = 416
#define P1_B 416
#define P1_W 428    // + 192 = 620
#define C2_B 620
#define C2_W 628    // + 96 = 724
#define P2_B 724
#define P2_W 728    // + 32 = 760
#define C3_B 760
#define C3_W 764    // + 16 = 780
#define R_B  780
#define R_W  784    // + 16 = 800
#define H_B  800
#define H_W  801    // + 4 = 805
#define U_TOTAL 805
__device__ float2 g_w[U_TOTAL];

typedef unsigned long long u64;

// ------------------------------- f32x2 helpers -----------------------------
__device__ __forceinline__ u64 pk2(float a, float b) {
    u64 r;
    asm("mov.b64 %0,{%1,%2};" : "=l"(r) : "f"(a), "f"(b));
    return r;
}
__device__ __forceinline__ void upk2(u64 v, float& a, float& b) {
    asm("mov.b64 {%0,%1},%2;" : "=f"(a), "=f"(b) : "l"(v));
}
__device__ __forceinline__ u64 ffma2(u64 a, u64 b, u64 c) {
    u64 d;
    asm("fma.rn.f32x2 %0,%1,%2,%3;" : "=l"(d) : "l"(a), "l"(b), "l"(c));
    return d;
}
__device__ __forceinline__ u64 fadd2(u64 a, u64 b) {
    u64 d;
    asm("add.rn.f32x2 %0,%1,%2;" : "=l"(d) : "l"(a), "l"(b));
    return d;
}
__device__ __forceinline__ float tanh_ap(float x) {
    float y;
    asm("tanh.approx.f32 %0,%1;" : "=f"(y) : "f"(x));
    return y;
}
__device__ __forceinline__ u64 tanh2(u64 v) {
    float a, b;
    upk2(v, a, b);
    return pk2(tanh_ap(a), tanh_ap(b));
}
__device__ __forceinline__ u64 relu2(u64 v) {
    float a, b;
    upk2(v, a, b);
    return pk2(fmaxf(a, 0.0f), fmaxf(b, 0.0f));
}

// dense layer on two packs (4 rows). Weight pairs fetched as aligned LDS.128.
template <int DIN, int DOUT, int BB, int WB, bool ACT>
__device__ __forceinline__ void layer2P(const u64* __restrict__ sw,
                                        const u64* __restrict__ a0,
                                        const u64* __restrict__ a1,
                                        u64* __restrict__ o0,
                                        u64* __restrict__ o1) {
#pragma unroll
    for (int j = 0; j < DOUT; j++) {
        u64 acc0 = sw[BB + j];                        // duplicated bias
        u64 acc1 = acc0;
#pragma unroll
        for (int i = 0; i < DIN; i += 2) {
            ulonglong2 w = *(const ulonglong2*)(sw + WB + j * DIN + i);
            acc0 = ffma2(a0[i], w.x, acc0);
            acc1 = ffma2(a1[i], w.x, acc1);
            acc0 = ffma2(a0[i + 1], w.y, acc0);
            acc1 = ffma2(a1[i + 1], w.y, acc1);
        }
        if (ACT) { acc0 = tanh2(acc0); acc1 = tanh2(acc1); }
        o0[j] = acc0;
        o1[j] = acc1;
    }
}

#define LDG4(dst, ptr)                                                        \
    asm volatile("ld.global.nc.v4.f32 {%0,%1,%2,%3},[%4];"                    \
                 : "=f"(dst.x), "=f"(dst.y), "=f"(dst.z), "=f"(dst.w)         \
                 : "l"(ptr))

// --------------------------- kernel A: stats + fold ------------------------
__global__ void __launch_bounds__(NT_STATS) k_statsfold(
    const float* __restrict__ x,
    const float* __restrict__ bn_g, const float* __restrict__ bn_b,
    const float* __restrict__ w_fm, const float* __restrict__ b_fm,
    const float* __restrict__ w_c1, const float* __restrict__ b_c1,
    const float* __restrict__ w_p1, const float* __restrict__ b_p1,
    const float* __restrict__ w_c2, const float* __restrict__ b_c2,
    const float* __restrict__ w_p2, const float* __restrict__ b_p2,
    const float* __restrict__ w_c3, const float* __restrict__ b_c3,
    const float* __restrict__ w_r,  const float* __restrict__ b_r,
    const float* __restrict__ w_h,  const float* __restrict__ b_h,
    float invB, int nrows) {
    int tid = threadIdx.x;
    int g = blockIdx.x * NT_STATS + tid;
    long base = (long)g * 4;                          // 4 rows / thread
    float s[8], q[8];
#pragma unroll
    for (int c = 0; c < 8; c++) { s[c] = 0.0f; q[c] = 0.0f; }
    {
        const float4* xv = (const float4*)(x + base * 8);
        // 8 loads pinned to distinct registers (true MLP = 8)
        float4 v0, v1, v2, v3, v4, v5, v6, v7;
        LDG4(v0, xv + 0); LDG4(v1, xv + 1);
        LDG4(v2, xv + 2); LDG4(v3, xv + 3);
        LDG4(v4, xv + 4); LDG4(v5, xv + 5);
        LDG4(v6, xv + 6); LDG4(v7, xv + 7);
        float4 lo[4] = {v0, v2, v4, v6};
        float4 hi[4] = {v1, v3, v5, v7};
#pragma unroll
        for (int r = 0; r < 4; r++) {
            float4 a = lo[r], b = hi[r];
            s[0] += a.x; q[0] = fmaf(a.x, a.x, q[0]);
            s[1] += a.y; q[1] = fmaf(a.y, a.y, q[1]);
            s[2] += a.z; q[2] = fmaf(a.z, a.z, q[2]);
            s[3] += a.w; q[3] = fmaf(a.w, a.w, q[3]);
            s[4] += b.x; q[4] = fmaf(b.x, b.x, q[4]);
            s[5] += b.y; q[5] = fmaf(b.y, b.y, q[5]);
            s[6] += b.z; q[6] = fmaf(b.z, b.z, q[6]);
            s[7] += b.w; q[7] = fmaf(b.w, b.w, q[7]);
        }
    }
#pragma unroll
    for (int c = 0; c < 8; c++) {
#pragma unroll
        for (int o = 16; o > 0; o >>= 1) {
            s[c] += __shfl_xor_sync(0xffffffffu, s[c], o);
            q[c] += __shfl_xor_sync(0xffffffffu, q[c], o);
        }
    }
    __shared__ float sm[8][16];
    int warp = tid >> 5, lane = tid & 31;
    if (lane == 0) {
#pragma unroll
        for (int c = 0; c < 8; c++) { sm[warp][c] = s[c]; sm[warp][8 + c] = q[c]; }
    }
    __syncthreads();
    if (tid < 16) {
        float acc = 0.0f;
#pragma unroll
        for (int w = 0; w < 8; w++) acc += sm[w][tid];
        g_partials[blockIdx.x * 16 + tid] = acc;
    }

    // ---- ticket: last block folds ----
    __shared__ unsigned int s_last;
    __threadfence();
    if (tid == 0) s_last = (atomicAdd(&g_ticket, 1u) == (unsigned)(gridDim.x - 1));
    __syncthreads();
    if (!s_last) return;

    __shared__ float s1[256];
    __shared__ float totals[16];
    __shared__ float scale[8], shift[8];
    {   // 16 cols x 16 chunks of 64, 8 independent accumulators per thread
        int col = tid & 15, chunk = tid >> 4;
        const float* p = g_partials + (chunk * 64) * 16 + col;
        float a0 = 0, a1 = 0, a2 = 0, a3 = 0, a4 = 0, a5 = 0, a6 = 0, a7 = 0;
#pragma unroll
        for (int b = 0; b < 64; b += 8) {
            a0 += p[(b + 0) * 16]; a1 += p[(b + 1) * 16];
            a2 += p[(b + 2) * 16]; a3 += p[(b + 3) * 16];
            a4 += p[(b + 4) * 16]; a5 += p[(b + 5) * 16];
            a6 += p[(b + 6) * 16]; a7 += p[(b + 7) * 16];
        }
        s1[col * 16 + chunk] = ((a0 + a1) + (a2 + a3)) + ((a4 + a5) + (a6 + a7));
    }
    __syncthreads();
    if (tid < 16) {
        float acc = 0.0f;
#pragma unroll
        for (int k = 0; k < 16; k++) acc += s1[tid * 16 + k];
        totals[tid] = acc;
    }
    __syncthreads();
    if (tid < 8) {
        float mu = totals[tid] * invB;
        float var = totals[8 + tid] * invB - mu * mu;
        float sc = bn_g[tid] * rsqrtf(var + 1e-5f);
        scale[tid] = sc;
        shift[tid] = bn_b[tid] - mu * sc;
    }
    __syncthreads();

    // folded first layer, layout B
    if (tid < 16) {
        float v = b_fm[tid];
#pragma unroll
        for (int i = 0; i < 8; i++) v += shift[i] * w_fm[i * 16 + tid];
        g_w[FM_B + tid] = make_float2(v, v);
    }
    if (tid < 128) {                                  // j = tid>>3, i = tid&7
        int j = tid >> 3, i = tid & 7;
        float v = scale[i] * w_fm[i * 16 + j];
        g_w[FM_W + j * 8 + i] = make_float2(v, v);
    }
    // generic layers: weights j-major
    {
        // c1: 16x16
        for (int idx = tid; idx < 256; idx += NT_STATS) {
            int j = idx >> 4, i = idx & 15;
            float v = w_c1[i * 16 + j];
            g_w[C1_W + j * 16 + i] = make_float2(v, v);
        }
        if (tid < 16) { float v = b_c1[tid]; g_w[C1_B + tid] = make_float2(v, v); }
        // p1: 16->12
        for (int idx = tid; idx < 192; idx += NT_STATS) {
            int j = idx >> 4, i = idx & 15;
            float v = w_p1[i * 12 + j];
            g_w[P1_W + j * 16 + i] = make_float2(v, v);
        }
        if (tid < 12) { float v = b_p1[tid]; g_w[P1_B + tid] = make_float2(v, v); }
        // c2: 12->8
        if (tid < 96) {
            int j = tid / 12, i = tid % 12;
            float v = w_c2[i * 8 + j];
            g_w[C2_W + j * 12 + i] = make_float2(v, v);
        }
        if (tid < 8) { float v = b_c2[tid]; g_w[C2_B + tid] = make_float2(v, v); }
        // p2: 8->4
        if (tid < 32) {
            int j = tid >> 3, i = tid & 7;
            float v = w_p2[i * 4 + j];
            g_w[P2_W + j * 8 + i] = make_float2(v, v);
        }
        if (tid < 4) { float v = b_p2[tid]; g_w[P2_B + tid] = make_float2(v, v); }
        // c3: 4->4
        if (tid < 16) {
            int j = tid >> 2, i = tid & 3;
            float v = w_c3[i * 4 + j];
            g_w[C3_W + j * 4 + i] = make_float2(v, v);
        }
        if (tid < 4) { float v = b_c3[tid]; g_w[C3_B + tid] = make_float2(v, v); }
        // r: 4->4
        if (tid < 16) {
            int j = tid >> 2, i = tid & 3;
            float v = w_r[i * 4 + j];
            g_w[R_W + j * 4 + i] = make_float2(v, v);
        }
        if (tid < 4) { float v = b_r[tid]; g_w[R_B + tid] = make_float2(v, v); }
        // h: 4->1
        if (tid < 4) { float v = w_h[tid]; g_w[H_W + tid] = make_float2(v, v); }
        if (tid == 0) { float v = b_h[0]; g_w[H_B] = make_float2(v, v); }
    }
    __syncthreads();
    if (tid == 0) g_ticket = 0;                       // reset for next replay
}

// ------------------------------- kernel B: main ----------------------------
__global__ void __launch_bounds__(NT_MAIN) k_main(const float* __restrict__ x,
                                                  float* __restrict__ out,
                                                  int nrows) {
    __shared__ __align__(16) u64 sw[U_TOTAL + 1];
    {
        const u64* gw = (const u64*)g_w;
        for (int i = threadIdx.x; i < U_TOTAL; i += NT_MAIN) sw[i] = gw[i];
    }
    __syncthreads();

    int t = blockIdx.x * NT_MAIN + threadIdx.x;
    long base = (long)t * 4;                          // 4 rows / thread
    if (base >= nrows) return;

    const float4* xv = (const float4*)(x + base * 8);
    float4 r0a = xv[0], r0b = xv[1];
    float4 r1a = xv[2], r1b = xv[3];
    float4 r2a = xv[4], r2b = xv[5];
    float4 r3a = xv[6], r3b = xv[7];

    u64 A0[16], A1[16], B0[16], B1[16];
    A0[0] = pk2(r0a.x, r1a.x); A1[0] = pk2(r2a.x, r3a.x);
    A0[1] = pk2(r0a.y, r1a.y); A1[1] = pk2(r2a.y, r3a.y);
    A0[2] = pk2(r0a.z, r1a.z); A1[2] = pk2(r2a.z, r3a.z);
    A0[3] = pk2(r0a.w, r1a.w); A1[3] = pk2(r2a.w, r3a.w);
    A0[4] = pk2(r0b.x, r1b.x); A1[4] = pk2(r2b.x, r3b.x);
    A0[5] = pk2(r0b.y, r1b.y); A1[5] = pk2(r2b.y, r3b.y);
    A0[6] = pk2(r0b.z, r1b.z); A1[6] = pk2(r2b.z, r3b.z);
    A0[7] = pk2(r0b.w, r1b.w); A1[7] = pk2(r2b.w, r3b.w);

    layer2P<8, 16, FM_B, FM_W, true>(sw, A0, A1, B0, B1);   // feature_map
    layer2P<16, 16, C1_B, C1_W, true>(sw, B0, B1, A0, A1);  // conv1
    layer2P<16, 12, P1_B, P1_W, true>(sw, A0, A1, B0, B1);  // pool1
    layer2P<12, 8, C2_B, C2_W, true>(sw, B0, B1, A0, A1);   // conv2
    layer2P<8, 4, P2_B, P2_W, true>(sw, A0, A1, B0, B1);    // pool2
    layer2P<4, 4, C3_B, C3_W, true>(sw, B0, B1, A0, A1);    // conv3
    layer2P<4, 4, R_B, R_W, false>(sw, A0, A1, B0, B1);     // residual pre-relu
#pragma unroll
    for (int j = 0; j < 4; j++) {
        A0[j] = fadd2(A0[j], relu2(B0[j]));
        A1[j] = fadd2(A1[j], relu2(B1[j]));
    }

    // head [4->1], sigmoid(z) = 0.5*tanh(0.5z)+0.5
    u64 acc0 = sw[H_B], acc1 = acc0;
#pragma unroll
    for (int i = 0; i < 4; i++) {
        u64 w = sw[H_W + i];
        acc0 = ffma2(A0[i], w, acc0);
        acc1 = ffma2(A1[i], w, acc1);
    }
    float z0, z1, z2, z3;
    upk2(acc0, z0, z1);
    upk2(acc1, z2, z3);
    float4 o;
    o.x = fmaf(0.5f, tanh_ap(0.5f * z0), 0.5f);
    o.y = fmaf(0.5f, tanh_ap(0.5f * z1), 0.5f);
    o.z = fmaf(0.5f, tanh_ap(0.5f * z2), 0.5f);
    o.w = fmaf(0.5f, tanh_ap(0.5f * z3), 0.5f);
    ((float4*)out)[t] = o;
}

// ------------------------------- launch ------------------------------------
extern "C" void kernel_launch(void* const* d_in, const int* in_sizes, int n_in,
                              void* d_out, int out_size) {
    const float* x    = (const float*)d_in[0];
    const float* bn_g = (const float*)d_in[1];
    const float* bn_b = (const float*)d_in[2];
    const float* w_fm = (const float*)d_in[3];
    const float* b_fm = (const float*)d_in[4];
    const float* w_c1 = (const float*)d_in[5];
    const float* b_c1 = (const float*)d_in[6];
    const float* w_p1 = (const float*)d_in[7];
    const float* b_p1 = (const float*)d_in[8];
    const float* w_c2 = (const float*)d_in[9];
    const float* b_c2 = (const float*)d_in[10];
    const float* w_p2 = (const float*)d_in[11];
    const float* b_p2 = (const float*)d_in[12];
    const float* w_c3 = (const float*)d_in[13];
    const float* b_c3 = (const float*)d_in[14];
    const float* w_r  = (const float*)d_in[15];
    const float* b_r  = (const float*)d_in[16];
    const float* w_h  = (const float*)d_in[17];
    const float* b_h  = (const float*)d_in[18];
    float* out = (float*)d_out;

    int nrows = in_sizes[0] / 8;                      // 1048576

    k_statsfold<<<NBLK_STATS, NT_STATS>>>(x, bn_g, bn_b, w_fm, b_fm,
                                          w_c1, b_c1, w_p1, b_p1, w_c2, b_c2,
                                          w_p2, b_p2, w_c3, b_c3, w_r, b_r,
                                          w_h, b_h, 1.0f / (float)nrows, nrows);
    k_main<<<(nrows / 4) / NT_MAIN, NT_MAIN>>>(x, out, nrows);
}